// round 8
// baseline (speedup 1.0000x reference)
#include <cuda_runtime.h>
#include <math.h>
#include <float.h>

#define XG 432
#define YG 496
#define CO 64
#define NPT 32
#define PMAX 64000
#define BMAX 4

// Scratch (no allocations allowed anywhere)
__device__ int   g_winner[BMAX * XG * YG];
__device__ float g_pooled[PMAX * CO];

typedef unsigned long long ull;

__device__ __forceinline__ ull fma2(ull a, ull b, ull c) {
    ull d; asm("fma.rn.f32x2 %0, %1, %2, %3;" : "=l"(d) : "l"(a), "l"(b), "l"(c));
    return d;
}
__device__ __forceinline__ float2 unpack2(ull v) {
    float2 f; asm("mov.b64 {%0, %1}, %2;" : "=f"(f.x), "=f"(f.y) : "l"(v));
    return f;
}

// ---------------------------------------------------------------------------
// Kernel 1: reset winner map
// ---------------------------------------------------------------------------
__global__ void init_winner_k(int n) {
    int i = blockIdx.x * blockDim.x + threadIdx.x;
    if (i < n) g_winner[i] = -1;
}

// ---------------------------------------------------------------------------
// Kernel 2: last-pillar-index-wins per BEV cell (deterministic via atomicMax)
// ---------------------------------------------------------------------------
__global__ void winner_k(const int* __restrict__ coors, int P, int B) {
    int p = blockIdx.x * blockDim.x + threadIdx.x;
    if (p >= P) return;
    int b = coors[4 * p + 0];
    int x = coors[4 * p + 1];
    int y = coors[4 * p + 2];
    if ((unsigned)b >= (unsigned)B || (unsigned)x >= XG || (unsigned)y >= YG)
        return;
    atomicMax(&g_winner[(b * XG + x) * YG + y], p);
}

// ---------------------------------------------------------------------------
// Kernel 3: PFN. Persistent-style grid-stride blocks, 128 threads,
// 2 pillars per iteration. Weights staged in smem ONCE per block.
// h1 stored pre-duplicated ({h,h} pairs) so the layer-2 f32x2 GEMM loop is
// pure 4x LDS.128 + 16x FFMA2 per k (no dup MOVs).
// ---------------------------------------------------------------------------
#define W2S 68        // s_w2t row stride (floats): 272B, 16B-aligned
#define H1S 132       // s_h1d row stride (floats): 528B, 16B-aligned

__global__ __launch_bounds__(128) void mlp_k(
    const float* __restrict__ pillars,
    const int*   __restrict__ coors,
    const int*   __restrict__ npoints,
    const float* __restrict__ W1, const float* __restrict__ g1,
    const float* __restrict__ b1, const float* __restrict__ m1,
    const float* __restrict__ v1,
    const float* __restrict__ W2, const float* __restrict__ g2,
    const float* __restrict__ b2, const float* __restrict__ m2,
    const float* __restrict__ v2, int P)
{
    extern __shared__ float smem[];
    float* s_w2t = smem;                    // [k][o]    64*68   = 4352
    float* s_h1d = smem + 4352;             // [k][2n]   64*132  = 8448 (dup pairs)
    float* s_w1t = s_h1d + 8448;            // [o][8]    512 (folded BN1 + bias)
    float* s_f   = s_w1t + 512;             // [n][9]    576
    float* s_s2  = s_f + 576;               // 64
    float* s_t2  = s_s2 + 64;               // 64

    const int tid  = threadIdx.x;
    const int w    = tid >> 5;
    const int lane = tid & 31;

    // ---- one-time staging ----
    #pragma unroll
    for (int i = tid; i < 4096; i += 128) {
        int o = i >> 6, k = i & 63;
        s_w2t[k * W2S + o] = W2[i];
    }
    if (tid < 64) {
        int o = tid;
        float s1 = g1[o] / sqrtf(v1[o] + 1e-5f);
        float t1 = b1[o] - m1[o] * s1;
        #pragma unroll
        for (int c = 0; c < 6; ++c) s_w1t[o * 8 + c] = W1[o * 6 + c] * s1;
        s_w1t[o * 8 + 6] = t1;
        s_w1t[o * 8 + 7] = 0.0f;
    } else {
        int o = tid - 64;
        float s2 = g2[o] / sqrtf(v2[o] + 1e-5f);
        s_s2[o] = s2;
        s_t2[o] = b2[o] - m2[o] * s2;
    }

    // layer-2 per-warp tile constants: warp -> (pillar w>>1, ch-half w&1)
    const int pg  = lane & 7;                 // point group (4 points)
    const int cg  = lane >> 3;                // channel group (8 ch)
    const int chb = (w & 1) * 32 + cg * 8;    // channel base
    const int hcol = ((w >> 1) * 32 + pg * 4) * 2;  // dup-float column

    const int nPairs = (P + 1) >> 1;
    for (int pair = blockIdx.x; pair < nPairs; pair += gridDim.x) {

        // ---- feature phase: warps 0,1 -> pillars 0,1 of this pair ----
        if (w < 2) {
            int pil = pair * 2 + w;
            if (pil < P) {
                float4 pt = *(const float4*)&pillars[(pil * 32 + lane) * 4];
                float sx = pt.x, sy = pt.y, sz = pt.z;
                #pragma unroll
                for (int off = 16; off > 0; off >>= 1) {
                    sx += __shfl_xor_sync(0xffffffffu, sx, off);
                    sy += __shfl_xor_sync(0xffffffffu, sy, off);
                    sz += __shfl_xor_sync(0xffffffffu, sz, off);
                }
                int   npf = npoints[pil];
                float fn  = (float)npf;
                float cx = sx / fn, cy = sy / fn, cz = sz / fn;
                float px = (float)coors[4 * pil + 1] * 0.16f + 0.08f;
                float py = (float)coors[4 * pil + 2] * 0.16f - 39.6f;
                float msk = (lane < npf) ? 1.0f : 0.0f;
                int n = w * 32 + lane;
                s_f[n * 9 + 0] = pt.z * msk;
                s_f[n * 9 + 1] = (pt.x - cx) * msk;
                s_f[n * 9 + 2] = (pt.y - cy) * msk;
                s_f[n * 9 + 3] = (pt.z - cz) * msk;
                s_f[n * 9 + 4] = (pt.x - px) * msk;
                s_f[n * 9 + 5] = (pt.y - py) * msk;
            }
        }
        __syncthreads();   // also fences prev iter's layer-2 reads of s_h1d

        // ---- layer 1: 6 -> 64 per point, ReLU, store dup pairs [o][2n] ----
        {
            int n = tid >> 1, half = tid & 1;
            const float* fp = &s_f[n * 9];
            float f0 = fp[0], f1 = fp[1], f2 = fp[2];
            float f3 = fp[3], f4 = fp[4], f5 = fp[5];
            #pragma unroll 8
            for (int j = 0; j < 32; ++j) {
                int o = half * 32 + j;
                float4 a = *(const float4*)&s_w1t[o * 8];
                float4 b = *(const float4*)&s_w1t[o * 8 + 4];
                float acc = b.z;                 // folded bias t1
                acc = fmaf(f0, a.x, acc);
                acc = fmaf(f1, a.y, acc);
                acc = fmaf(f2, a.z, acc);
                acc = fmaf(f3, a.w, acc);
                acc = fmaf(f4, b.x, acc);
                acc = fmaf(f5, b.y, acc);
                float h = fmaxf(acc, 0.0f);
                *(float2*)&s_h1d[o * H1S + 2 * n] = make_float2(h, h);
            }
        }
        __syncthreads();

        // ---- layer 2: 64x64 f32x2 GEMM, 4 pts x 8 ch per lane ----
        ull acc[4][4];
        #pragma unroll
        for (int p = 0; p < 4; ++p)
            #pragma unroll
            for (int j = 0; j < 4; ++j) acc[p][j] = 0ULL;

        #pragma unroll 4
        for (int k = 0; k < 64; ++k) {
            ulonglong2 H0 = *(const ulonglong2*)&s_h1d[k * H1S + hcol];
            ulonglong2 H1 = *(const ulonglong2*)&s_h1d[k * H1S + hcol + 4];
            ulonglong2 W0 = *(const ulonglong2*)&s_w2t[k * W2S + chb];
            ulonglong2 Wv = *(const ulonglong2*)&s_w2t[k * W2S + chb + 4];
            acc[0][0] = fma2(H0.x, W0.x, acc[0][0]);
            acc[0][1] = fma2(H0.x, W0.y, acc[0][1]);
            acc[0][2] = fma2(H0.x, Wv.x, acc[0][2]);
            acc[0][3] = fma2(H0.x, Wv.y, acc[0][3]);
            acc[1][0] = fma2(H0.y, W0.x, acc[1][0]);
            acc[1][1] = fma2(H0.y, W0.y, acc[1][1]);
            acc[1][2] = fma2(H0.y, Wv.x, acc[1][2]);
            acc[1][3] = fma2(H0.y, Wv.y, acc[1][3]);
            acc[2][0] = fma2(H1.x, W0.x, acc[2][0]);
            acc[2][1] = fma2(H1.x, W0.y, acc[2][1]);
            acc[2][2] = fma2(H1.x, Wv.x, acc[2][2]);
            acc[2][3] = fma2(H1.x, Wv.y, acc[2][3]);
            acc[3][0] = fma2(H1.y, W0.x, acc[3][0]);
            acc[3][1] = fma2(H1.y, W0.y, acc[3][1]);
            acc[3][2] = fma2(H1.y, Wv.x, acc[3][2]);
            acc[3][3] = fma2(H1.y, Wv.y, acc[3][3]);
        }

        // ---- epilogue: BN2 + max over 4 local points, shfl-reduce over pg ----
        float mx[8];
        #pragma unroll
        for (int j = 0; j < 4; ++j) {
            float s2l = s_s2[chb + 2 * j],     t2l = s_t2[chb + 2 * j];
            float s2h = s_s2[chb + 2 * j + 1], t2h = s_t2[chb + 2 * j + 1];
            float ml = -FLT_MAX, mh = -FLT_MAX;
            #pragma unroll
            for (int p = 0; p < 4; ++p) {
                float2 v = unpack2(acc[p][j]);
                ml = fmaxf(ml, fmaf(v.x, s2l, t2l));
                mh = fmaxf(mh, fmaf(v.y, s2h, t2h));
            }
            mx[2 * j]     = ml;
            mx[2 * j + 1] = mh;
        }
        #pragma unroll
        for (int off = 1; off < 8; off <<= 1) {
            #pragma unroll
            for (int i = 0; i < 8; ++i)
                mx[i] = fmaxf(mx[i], __shfl_xor_sync(0xffffffffu, mx[i], off));
        }
        if (pg == 0) {
            int pil = pair * 2 + (w >> 1);
            if (pil < P) {
                *(float4*)&g_pooled[pil * 64 + chb] =
                    make_float4(mx[0], mx[1], mx[2], mx[3]);
                *(float4*)&g_pooled[pil * 64 + chb + 4] =
                    make_float4(mx[4], mx[5], mx[6], mx[7]);
            }
        }
    }
}

// ---------------------------------------------------------------------------
// Kernel 4: emit pseudo-image (B, C, Y, X). grid = (YG, B), 128 threads.
// Thread owns 4 consecutive x. Per c-quad: 4 LDG.128 gathers (L1-resident),
// register transpose, 4 coalesced STG.128.
// ---------------------------------------------------------------------------
__global__ __launch_bounds__(128) void emit_k(float* __restrict__ out) {
    __shared__ int s_wi[XG];
    const int y = blockIdx.x;
    const int b = blockIdx.y;
    for (int x = threadIdx.x; x < XG; x += 128)
        s_wi[x] = g_winner[(b * XG + x) * YG + y];
    __syncthreads();

    const int t = threadIdx.x;
    if (t >= XG / 4) return;   // 108 active threads
    const int x0 = t * 4;

    const float* pp[4];
    bool ok[4];
    #pragma unroll
    for (int i = 0; i < 4; ++i) {
        int wi = s_wi[x0 + i];
        ok[i] = (wi >= 0);
        pp[i] = g_pooled + (ok[i] ? wi : 0) * 64;
    }

    const float4 z4 = make_float4(0.f, 0.f, 0.f, 0.f);
    float* op = out + ((long long)b * CO * YG + y) * XG + x0;
    const long long cstride = (long long)YG * XG;

    #pragma unroll 1
    for (int cq = 0; cq < 16; ++cq) {
        float4 v[4];
        #pragma unroll
        for (int i = 0; i < 4; ++i)
            v[i] = ok[i] ? *(const float4*)(pp[i] + cq * 4) : z4;
        *(float4*)op = make_float4(v[0].x, v[1].x, v[2].x, v[3].x); op += cstride;
        *(float4*)op = make_float4(v[0].y, v[1].y, v[2].y, v[3].y); op += cstride;
        *(float4*)op = make_float4(v[0].z, v[1].z, v[2].z, v[3].z); op += cstride;
        *(float4*)op = make_float4(v[0].w, v[1].w, v[2].w, v[3].w); op += cstride;
    }
}

// ---------------------------------------------------------------------------
// kernel_launch — graph-capturable, allocation-free
// ---------------------------------------------------------------------------
extern "C" void kernel_launch(void* const* d_in, const int* in_sizes, int n_in,
                              void* d_out, int out_size) {
    const float* pillars = (const float*)d_in[0];
    const int*   coors   = (const int*)d_in[1];
    const int*   npts    = (const int*)d_in[2];

    int wbase = (in_sizes[3] == 384) ? 3 : 4;  // skip batch_size slot if present
    const float* W1 = (const float*)d_in[wbase + 0];
    const float* g1 = (const float*)d_in[wbase + 1];
    const float* b1 = (const float*)d_in[wbase + 2];
    const float* m1 = (const float*)d_in[wbase + 3];
    const float* v1 = (const float*)d_in[wbase + 4];
    const float* W2 = (const float*)d_in[wbase + 5];
    const float* g2 = (const float*)d_in[wbase + 6];
    const float* b2 = (const float*)d_in[wbase + 7];
    const float* m2 = (const float*)d_in[wbase + 8];
    const float* v2 = (const float*)d_in[wbase + 9];

    int P = in_sizes[0] / (NPT * 4);
    int B = out_size / (CO * XG * YG);
    if (B > BMAX) B = BMAX;
    if (P > PMAX) P = PMAX;
    int win = B * XG * YG;

    const int smemBytes = (4352 + 8448 + 512 + 576 + 64 + 64) * 4;  // 56064
    cudaFuncSetAttribute(mlp_k, cudaFuncAttributeMaxDynamicSharedMemorySize,
                         smemBytes);

    int nPairs = (P + 1) / 2;
    int grid = 592;                  // 4 blocks/SM x 148 SMs
    if (grid > nPairs) grid = nPairs;

    init_winner_k<<<(win + 255) / 256, 256>>>(win);
    winner_k<<<(P + 255) / 256, 256>>>(coors, P, B);
    mlp_k<<<grid, 128, smemBytes>>>(pillars, coors, npts,
                                    W1, g1, b1, m1, v1, W2, g2, b2, m2, v2, P);
    emit_k<<<dim3(YG, B), 128>>>((float*)d_out);
}

// round 9
// speedup vs baseline: 1.5640x; 1.5640x over previous
#include <cuda_runtime.h>
#include <math.h>
#include <float.h>

#define XG 432
#define YG 496
#define CO 64
#define NPT 32
#define PMAX 64000
#define BMAX 4

// Scratch (no allocations allowed anywhere)
__device__ int   g_winner[BMAX * XG * YG];
__device__ float g_pooled[PMAX * CO];

typedef unsigned long long ull;

__device__ __forceinline__ ull dup2(float x) {
    ull r; asm("mov.b64 %0, {%1, %1};" : "=l"(r) : "f"(x)); return r;
}
__device__ __forceinline__ ull fma2(ull a, ull b, ull c) {
    ull d; asm("fma.rn.f32x2 %0, %1, %2, %3;" : "=l"(d) : "l"(a), "l"(b), "l"(c));
    return d;
}
__device__ __forceinline__ float2 unpack2(ull v) {
    float2 f; asm("mov.b64 {%0, %1}, %2;" : "=f"(f.x), "=f"(f.y) : "l"(v));
    return f;
}

// ---------------------------------------------------------------------------
// Kernel 1: reset winner map
// ---------------------------------------------------------------------------
__global__ void init_winner_k(int n) {
    int i = blockIdx.x * blockDim.x + threadIdx.x;
    if (i < n) g_winner[i] = -1;
}

// ---------------------------------------------------------------------------
// Kernel 2: last-pillar-index-wins per BEV cell (deterministic via atomicMax)
// ---------------------------------------------------------------------------
__global__ void winner_k(const int* __restrict__ coors, int P, int B) {
    int p = blockIdx.x * blockDim.x + threadIdx.x;
    if (p >= P) return;
    int b = coors[4 * p + 0];
    int x = coors[4 * p + 1];
    int y = coors[4 * p + 2];
    if ((unsigned)b >= (unsigned)B || (unsigned)x >= XG || (unsigned)y >= YG)
        return;
    atomicMax(&g_winner[(b * XG + x) * YG + y], p);
}

// ---------------------------------------------------------------------------
// Kernel 3: PFN. 128 threads = 4 warps, 8 pillars per block (8000 blocks).
// Each warp owns 2 pillars end-to-end: features in regs -> layer1 -> own
// s_h1 segment -> f32x2 GEMM (lane tile 8pt x 16ch) -> max -> store.
// Only ONE __syncthreads (after W2 staging); warp phases use __syncwarp.
// ---------------------------------------------------------------------------
#define W2S 68        // s_w2t row stride (floats): 272B
#define H1S 260       // s_h1 row stride (floats): 1040B, 16B-aligned, bank-rot

__global__ __launch_bounds__(128) void mlp_k(
    const float* __restrict__ pillars,
    const int*   __restrict__ coors,
    const int*   __restrict__ npoints,
    const float* __restrict__ W1, const float* __restrict__ g1,
    const float* __restrict__ b1, const float* __restrict__ m1,
    const float* __restrict__ v1,
    const float* __restrict__ W2, const float* __restrict__ g2,
    const float* __restrict__ b2, const float* __restrict__ m2,
    const float* __restrict__ v2, int P)
{
    extern __shared__ float smem[];
    float* s_w2t = smem;                    // [k][o]   64*68  = 4352
    float* s_h1  = smem + 4352;             // [k][n]   64*260 = 16640 (n=256 pts)
    float* s_w1t = s_h1 + 64 * H1S;         // [o][8]   512 (folded BN1 + bias)
    float* s_s2  = s_w1t + 512;             // 64
    float* s_t2  = s_s2 + 64;               // 64
    // total 21632 floats = 86528 B

    const int tid  = threadIdx.x;
    const int w    = tid >> 5;
    const int lane = tid & 31;

    // ---- one-time staging (only block-wide coupling) ----
    #pragma unroll
    for (int i = tid; i < 4096; i += 128) {
        int o = i >> 6, k = i & 63;
        s_w2t[k * W2S + o] = W2[i];
    }
    if (tid < 64) {
        int o = tid;
        float s1 = g1[o] / sqrtf(v1[o] + 1e-5f);
        float t1 = b1[o] - m1[o] * s1;
        #pragma unroll
        for (int c = 0; c < 6; ++c) s_w1t[o * 8 + c] = W1[o * 6 + c] * s1;
        s_w1t[o * 8 + 6] = t1;
        s_w1t[o * 8 + 7] = 0.0f;
    } else {
        int o = tid - 64;
        float s2 = g2[o] / sqrtf(v2[o] + 1e-5f);
        s_s2[o] = s2;
        s_t2[o] = b2[o] - m2[o] * s2;
    }
    __syncthreads();

    const int pilBase = blockIdx.x * 8 + w * 2;

    // ---- feature + layer-1 for this warp's 2 pillars (lane = point) ----
    #pragma unroll
    for (int i = 0; i < 2; ++i) {
        int pil = pilBase + i;
        if (pil < P) {
            float4 pt = *(const float4*)&pillars[(pil * 32 + lane) * 4];
            float sx = pt.x, sy = pt.y, sz = pt.z;
            #pragma unroll
            for (int off = 16; off > 0; off >>= 1) {
                sx += __shfl_xor_sync(0xffffffffu, sx, off);
                sy += __shfl_xor_sync(0xffffffffu, sy, off);
                sz += __shfl_xor_sync(0xffffffffu, sz, off);
            }
            int   npf = npoints[pil];
            float fn  = (float)npf;
            float cx = sx / fn, cy = sy / fn, cz = sz / fn;
            float px = (float)coors[4 * pil + 1] * 0.16f + 0.08f;
            float py = (float)coors[4 * pil + 2] * 0.16f - 39.6f;
            float msk = (lane < npf) ? 1.0f : 0.0f;
            float f0 = pt.z * msk;
            float f1 = (pt.x - cx) * msk;
            float f2 = (pt.y - cy) * msk;
            float f3 = (pt.z - cz) * msk;
            float f4 = (pt.x - px) * msk;
            float f5 = (pt.y - py) * msk;

            // layer 1: 6 -> 64 channels for this point, ReLU, store [o][n]
            float* hcol = &s_h1[w * 64 + i * 32 + lane];
            #pragma unroll 16
            for (int o = 0; o < 64; ++o) {
                float4 a = *(const float4*)&s_w1t[o * 8];      // broadcast
                float4 b = *(const float4*)&s_w1t[o * 8 + 4];  // broadcast
                float acc = b.z;                 // folded bias t1
                acc = fmaf(f0, a.x, acc);
                acc = fmaf(f1, a.y, acc);
                acc = fmaf(f2, a.z, acc);
                acc = fmaf(f3, a.w, acc);
                acc = fmaf(f4, b.x, acc);
                acc = fmaf(f5, b.y, acc);
                hcol[o * H1S] = fmaxf(acc, 0.0f);
            }
        }
    }
    __syncwarp();

    // ---- layer 2: 64x64 f32x2 GEMM. Lane tile: 8 pts x 16 ch.
    //      warp tile: 64 pts (2 pillars) x 64 ch.
    //      ptg = lane>>2 (8 groups of 8 pts), chg = lane&3 (4 groups of 16 ch)
    const int ptg = lane >> 2;
    const int chg = lane & 3;
    const int chb = chg * 16;

    const float* hp = &s_h1[w * 64 + ptg * 8];
    const ull*   wp = (const ull*)&s_w2t[chb];

    ull acc[8][8];
    #pragma unroll
    for (int p = 0; p < 8; ++p)
        #pragma unroll
        for (int c = 0; c < 8; ++c) acc[p][c] = 0ULL;

    #pragma unroll 2
    for (int k = 0; k < 64; ++k) {
        float4 ha = *(const float4*)hp;
        float4 hb = *(const float4*)(hp + 4);
        ull hd[8];
        hd[0] = dup2(ha.x); hd[1] = dup2(ha.y);
        hd[2] = dup2(ha.z); hd[3] = dup2(ha.w);
        hd[4] = dup2(hb.x); hd[5] = dup2(hb.y);
        hd[6] = dup2(hb.z); hd[7] = dup2(hb.w);
        ulonglong2 w01 = *(const ulonglong2*)(wp);
        ulonglong2 w23 = *(const ulonglong2*)(wp + 2);
        ulonglong2 w45 = *(const ulonglong2*)(wp + 4);
        ulonglong2 w67 = *(const ulonglong2*)(wp + 6);
        ull wv[8] = {w01.x, w01.y, w23.x, w23.y, w45.x, w45.y, w67.x, w67.y};
        #pragma unroll
        for (int p = 0; p < 8; ++p) {
            #pragma unroll
            for (int c = 0; c < 8; ++c)
                acc[p][c] = fma2(hd[p], wv[c], acc[p][c]);
        }
        hp += H1S;
        wp += W2S / 2;
    }

    // ---- epilogue: BN2, max over lane's 8 points, shfl over ptg in pillar ----
    float mx[16];
    #pragma unroll
    for (int c = 0; c < 8; ++c) {
        float s2l = s_s2[chb + 2 * c],     t2l = s_t2[chb + 2 * c];
        float s2h = s_s2[chb + 2 * c + 1], t2h = s_t2[chb + 2 * c + 1];
        float ml = -FLT_MAX, mh = -FLT_MAX;
        #pragma unroll
        for (int p = 0; p < 8; ++p) {
            float2 v = unpack2(acc[p][c]);
            ml = fmaxf(ml, fmaf(v.x, s2l, t2l));
            mh = fmaxf(mh, fmaf(v.y, s2h, t2h));
        }
        mx[2 * c]     = ml;
        mx[2 * c + 1] = mh;
    }
    // reduce over ptg&3 (lanes xor 4, xor 8): pillar A = lanes 0..15, B = 16..31
    #pragma unroll
    for (int off = 4; off <= 8; off <<= 1) {
        #pragma unroll
        for (int i = 0; i < 16; ++i)
            mx[i] = fmaxf(mx[i], __shfl_xor_sync(0xffffffffu, mx[i], off));
    }
    if ((lane & 12) == 0) {
        int pil = pilBase + (lane >> 4);
        if (pil < P) {
            float* dst = &g_pooled[pil * 64 + chb];
            *(float4*)(dst)      = make_float4(mx[0],  mx[1],  mx[2],  mx[3]);
            *(float4*)(dst + 4)  = make_float4(mx[4],  mx[5],  mx[6],  mx[7]);
            *(float4*)(dst + 8)  = make_float4(mx[8],  mx[9],  mx[10], mx[11]);
            *(float4*)(dst + 12) = make_float4(mx[12], mx[13], mx[14], mx[15]);
        }
    }
}

// ---------------------------------------------------------------------------
// Kernel 4: emit pseudo-image (B, C, Y, X). grid = (YG, B), 128 threads.
// Thread owns 4 consecutive x. Per c-quad: 4 LDG.128 gathers (L2-resident),
// register transpose, 4 coalesced STG.128.
// ---------------------------------------------------------------------------
__global__ __launch_bounds__(128) void emit_k(float* __restrict__ out) {
    __shared__ int s_wi[XG];
    const int y = blockIdx.x;
    const int b = blockIdx.y;
    for (int x = threadIdx.x; x < XG; x += 128)
        s_wi[x] = g_winner[(b * XG + x) * YG + y];
    __syncthreads();

    const int t = threadIdx.x;
    if (t >= XG / 4) return;   // 108 active threads
    const int x0 = t * 4;

    const float* pp[4];
    bool ok[4];
    #pragma unroll
    for (int i = 0; i < 4; ++i) {
        int wi = s_wi[x0 + i];
        ok[i] = (wi >= 0);
        pp[i] = g_pooled + (ok[i] ? wi : 0) * 64;
    }

    const float4 z4 = make_float4(0.f, 0.f, 0.f, 0.f);
    float* op = out + ((long long)b * CO * YG + y) * XG + x0;
    const long long cstride = (long long)YG * XG;

    #pragma unroll 1
    for (int cq = 0; cq < 16; ++cq) {
        float4 v[4];
        #pragma unroll
        for (int i = 0; i < 4; ++i)
            v[i] = ok[i] ? *(const float4*)(pp[i] + cq * 4) : z4;
        *(float4*)op = make_float4(v[0].x, v[1].x, v[2].x, v[3].x); op += cstride;
        *(float4*)op = make_float4(v[0].y, v[1].y, v[2].y, v[3].y); op += cstride;
        *(float4*)op = make_float4(v[0].z, v[1].z, v[2].z, v[3].z); op += cstride;
        *(float4*)op = make_float4(v[0].w, v[1].w, v[2].w, v[3].w); op += cstride;
    }
}

// ---------------------------------------------------------------------------
// kernel_launch — graph-capturable, allocation-free
// ---------------------------------------------------------------------------
extern "C" void kernel_launch(void* const* d_in, const int* in_sizes, int n_in,
                              void* d_out, int out_size) {
    const float* pillars = (const float*)d_in[0];
    const int*   coors   = (const int*)d_in[1];
    const int*   npts    = (const int*)d_in[2];

    int wbase = (in_sizes[3] == 384) ? 3 : 4;  // skip batch_size slot if present
    const float* W1 = (const float*)d_in[wbase + 0];
    const float* g1 = (const float*)d_in[wbase + 1];
    const float* b1 = (const float*)d_in[wbase + 2];
    const float* m1 = (const float*)d_in[wbase + 3];
    const float* v1 = (const float*)d_in[wbase + 4];
    const float* W2 = (const float*)d_in[wbase + 5];
    const float* g2 = (const float*)d_in[wbase + 6];
    const float* b2 = (const float*)d_in[wbase + 7];
    const float* m2 = (const float*)d_in[wbase + 8];
    const float* v2 = (const float*)d_in[wbase + 9];

    int P = in_sizes[0] / (NPT * 4);
    int B = out_size / (CO * XG * YG);
    if (B > BMAX) B = BMAX;
    if (P > PMAX) P = PMAX;
    int win = B * XG * YG;

    const int smemBytes = (4352 + 64 * H1S + 512 + 64 + 64) * 4;  // 86528
    cudaFuncSetAttribute(mlp_k, cudaFuncAttributeMaxDynamicSharedMemorySize,
                         smemBytes);

    init_winner_k<<<(win + 255) / 256, 256>>>(win);
    winner_k<<<(P + 255) / 256, 256>>>(coors, P, B);
    mlp_k<<<(P + 7) / 8, 128, smemBytes>>>(pillars, coors, npts,
                                           W1, g1, b1, m1, v1,
                                           W2, g2, b2, m2, v2, P);
    emit_k<<<dim3(YG, B), 128>>>((float*)d_out);
}

// round 10
// speedup vs baseline: 2.6427x; 1.6897x over previous
#include <cuda_runtime.h>
#include <cuda_bf16.h>
#include <math.h>
#include <float.h>

#define XG 432
#define YG 496
#define CO 64
#define NPT 32
#define PMAX 64000
#define BMAX 4

// Scratch (no allocations allowed anywhere)
__device__ int   g_winner[BMAX * XG * YG];
__device__ float g_pooled[PMAX * CO];

// ---------------------------------------------------------------------------
// mma.sync m16n8k16 row.col f32 += bf16*bf16
// ---------------------------------------------------------------------------
__device__ __forceinline__ void mma_bf16(float d[4],
                                         unsigned a0, unsigned a1,
                                         unsigned a2, unsigned a3,
                                         unsigned b0, unsigned b1) {
    asm volatile(
        "mma.sync.aligned.m16n8k16.row.col.f32.bf16.bf16.f32 "
        "{%0,%1,%2,%3}, {%4,%5,%6,%7}, {%8,%9}, {%0,%1,%2,%3};"
        : "+f"(d[0]), "+f"(d[1]), "+f"(d[2]), "+f"(d[3])
        : "r"(a0), "r"(a1), "r"(a2), "r"(a3), "r"(b0), "r"(b1));
}

// ---------------------------------------------------------------------------
// Kernel 1: reset winner map
// ---------------------------------------------------------------------------
__global__ void init_winner_k(int n) {
    int i = blockIdx.x * blockDim.x + threadIdx.x;
    if (i < n) g_winner[i] = -1;
}

// ---------------------------------------------------------------------------
// Kernel 2: last-pillar-index-wins per BEV cell (deterministic via atomicMax)
// ---------------------------------------------------------------------------
__global__ void winner_k(const int* __restrict__ coors, int P, int B) {
    int p = blockIdx.x * blockDim.x + threadIdx.x;
    if (p >= P) return;
    int b = coors[4 * p + 0];
    int x = coors[4 * p + 1];
    int y = coors[4 * p + 2];
    if ((unsigned)b >= (unsigned)B || (unsigned)x >= XG || (unsigned)y >= YG)
        return;
    atomicMax(&g_winner[(b * XG + x) * YG + y], p);
}

// ---------------------------------------------------------------------------
// Kernel 3: PFN with split-bf16 tensor-core layer 2.
// 256 threads = 8 warps = 8 pillars per block. Warp owns a pillar end-to-end.
//   layer1: lane = channel-pair, features shfl-broadcast, fp32 SIMT, folded BN1
//           -> h1 stored as bf16 hi/lo [pt][k], stride 72 (conflict-free).
//   layer2: D[o][pt] = W2[o][k] * h1[pt][k]^T via mma.sync m16n8k16,
//           3 passes (hi*hi + hi*lo + lo*hi) for fp32-grade accuracy.
//   epilogue: BN2 (sign-safe via max&min), max over points in-fragment.
// ---------------------------------------------------------------------------
#define HS 72   // bf16 stride per row (144 B): (4g+t4) banks, conflict-free

__global__ __launch_bounds__(256) void mlp_k(
    const float* __restrict__ pillars,
    const int*   __restrict__ coors,
    const int*   __restrict__ npoints,
    const float* __restrict__ W1, const float* __restrict__ g1,
    const float* __restrict__ b1, const float* __restrict__ m1,
    const float* __restrict__ v1,
    const float* __restrict__ W2, const float* __restrict__ g2,
    const float* __restrict__ b2, const float* __restrict__ m2,
    const float* __restrict__ v2, int P)
{
    extern __shared__ char smem[];
    __nv_bfloat16* s_w2hi = (__nv_bfloat16*)smem;          // [64][HS]
    __nv_bfloat16* s_w2lo = s_w2hi + 64 * HS;              // [64][HS]
    __nv_bfloat16* s_h1hi = s_w2lo + 64 * HS;              // [8][32][HS]
    __nv_bfloat16* s_h1lo = s_h1hi + 8 * 32 * HS;          // [8][32][HS]
    float* s_s2 = (float*)(s_h1lo + 8 * 32 * HS);          // [64]
    float* s_t2 = s_s2 + 64;                               // [64]

    const int tid  = threadIdx.x;
    const int w    = tid >> 5;
    const int lane = tid & 31;
    const int g    = lane >> 2;     // group id (row within fragment)
    const int t4   = lane & 3;      // thread-in-group (col pair)

    // ---- stage W2 as bf16 hi/lo (once per block) ----
    for (int i = tid; i < 4096; i += 256) {
        int o = i >> 6, k = i & 63;
        float wv = W2[i];
        __nv_bfloat16 hi = __float2bfloat16_rn(wv);
        s_w2hi[o * HS + k] = hi;
        s_w2lo[o * HS + k] = __float2bfloat16_rn(wv - __bfloat162float(hi));
    }
    if (tid < 64) {
        float s2v = g2[tid] / sqrtf(v2[tid] + 1e-5f);
        s_s2[tid] = s2v;
        s_t2[tid] = b2[tid] - m2[tid] * s2v;
    }
    __syncthreads();   // last block-wide sync

    const int pil = blockIdx.x * 8 + w;
    if (pil >= P) return;

    // ---- features (lane = point) ----
    float4 pt = *(const float4*)&pillars[(pil * 32 + lane) * 4];
    float sx = pt.x, sy = pt.y, sz = pt.z;
    #pragma unroll
    for (int off = 16; off > 0; off >>= 1) {
        sx += __shfl_xor_sync(0xffffffffu, sx, off);
        sy += __shfl_xor_sync(0xffffffffu, sy, off);
        sz += __shfl_xor_sync(0xffffffffu, sz, off);
    }
    const int   npf = npoints[pil];
    const float fn  = (float)npf;
    const float cx = sx / fn, cy = sy / fn, cz = sz / fn;
    const float px = (float)coors[4 * pil + 1] * 0.16f + 0.08f;
    const float py = (float)coors[4 * pil + 2] * 0.16f - 39.6f;
    const float msk = (lane < npf) ? 1.0f : 0.0f;
    float f0 = pt.z * msk;
    float f1 = (pt.x - cx) * msk;
    float f2 = (pt.y - cy) * msk;
    float f3 = (pt.z - cz) * msk;
    float f4 = (pt.x - px) * msk;
    float f5 = (pt.y - py) * msk;

    // ---- layer-1 weights for this lane's 2 channels (folded BN1) ----
    const int c0 = 2 * lane, c1 = c0 + 1;
    float s1a = g1[c0] / sqrtf(v1[c0] + 1e-5f);
    float s1b = g1[c1] / sqrtf(v1[c1] + 1e-5f);
    float t1a = b1[c0] - m1[c0] * s1a;
    float t1b = b1[c1] - m1[c1] * s1b;
    float wa[6], wb[6];
    #pragma unroll
    for (int j = 0; j < 6; ++j) {
        wa[j] = W1[c0 * 6 + j] * s1a;
        wb[j] = W1[c1 * 6 + j] * s1b;
    }

    __nv_bfloat16* h1hi = s_h1hi + w * 32 * HS;
    __nv_bfloat16* h1lo = s_h1lo + w * 32 * HS;

    // ---- layer 1: per point p, this lane computes channels c0,c1 ----
    #pragma unroll 4
    for (int p = 0; p < 32; ++p) {
        float e0 = __shfl_sync(0xffffffffu, f0, p);
        float e1 = __shfl_sync(0xffffffffu, f1, p);
        float e2 = __shfl_sync(0xffffffffu, f2, p);
        float e3 = __shfl_sync(0xffffffffu, f3, p);
        float e4 = __shfl_sync(0xffffffffu, f4, p);
        float e5 = __shfl_sync(0xffffffffu, f5, p);
        float ha = t1a, hb = t1b;
        ha = fmaf(e0, wa[0], ha);  hb = fmaf(e0, wb[0], hb);
        ha = fmaf(e1, wa[1], ha);  hb = fmaf(e1, wb[1], hb);
        ha = fmaf(e2, wa[2], ha);  hb = fmaf(e2, wb[2], hb);
        ha = fmaf(e3, wa[3], ha);  hb = fmaf(e3, wb[3], hb);
        ha = fmaf(e4, wa[4], ha);  hb = fmaf(e4, wb[4], hb);
        ha = fmaf(e5, wa[5], ha);  hb = fmaf(e5, wb[5], hb);
        ha = fmaxf(ha, 0.0f);
        hb = fmaxf(hb, 0.0f);
        __nv_bfloat162 hi2 = __floats2bfloat162_rn(ha, hb);
        float2 hf = __bfloat1622float2(hi2);
        __nv_bfloat162 lo2 = __floats2bfloat162_rn(ha - hf.x, hb - hf.y);
        *(__nv_bfloat162*)&h1hi[p * HS + c0] = hi2;   // bank = lane, CF
        *(__nv_bfloat162*)&h1lo[p * HS + c0] = lo2;
    }
    __syncwarp();

    // ---- layer 2: D[64 o][32 pt] via 4 mtiles x 4 ntiles x 4 ktiles ----
    float d[4][4][4];
    #pragma unroll
    for (int m = 0; m < 4; ++m)
        #pragma unroll
        for (int n = 0; n < 4; ++n)
            #pragma unroll
            for (int r = 0; r < 4; ++r) d[m][n][r] = 0.0f;

    #pragma unroll
    for (int kt = 0; kt < 4; ++kt) {
        const int kA = kt * 16 + 2 * t4;
        const int kB = kA + 8;

        unsigned ahi[4][4];
        #pragma unroll
        for (int m = 0; m < 4; ++m) {
            int r0 = (16 * m + g) * HS, r1 = r0 + 8 * HS;
            ahi[m][0] = *(const unsigned*)&s_w2hi[r0 + kA];
            ahi[m][1] = *(const unsigned*)&s_w2hi[r1 + kA];
            ahi[m][2] = *(const unsigned*)&s_w2hi[r0 + kB];
            ahi[m][3] = *(const unsigned*)&s_w2hi[r1 + kB];
        }
        unsigned bhi[4][2], blo[4][2];
        #pragma unroll
        for (int n = 0; n < 4; ++n) {
            int pr = (8 * n + g) * HS;
            bhi[n][0] = *(const unsigned*)&h1hi[pr + kA];
            bhi[n][1] = *(const unsigned*)&h1hi[pr + kB];
            blo[n][0] = *(const unsigned*)&h1lo[pr + kA];
            blo[n][1] = *(const unsigned*)&h1lo[pr + kB];
        }
        // hi*hi and hi*lo passes
        #pragma unroll
        for (int m = 0; m < 4; ++m)
            #pragma unroll
            for (int n = 0; n < 4; ++n) {
                mma_bf16(d[m][n], ahi[m][0], ahi[m][1], ahi[m][2], ahi[m][3],
                         bhi[n][0], bhi[n][1]);
                mma_bf16(d[m][n], ahi[m][0], ahi[m][1], ahi[m][2], ahi[m][3],
                         blo[n][0], blo[n][1]);
            }
        // lo*hi pass (load alo after ahi is dead for this ktile)
        unsigned alo[4][4];
        #pragma unroll
        for (int m = 0; m < 4; ++m) {
            int r0 = (16 * m + g) * HS, r1 = r0 + 8 * HS;
            alo[m][0] = *(const unsigned*)&s_w2lo[r0 + kA];
            alo[m][1] = *(const unsigned*)&s_w2lo[r1 + kA];
            alo[m][2] = *(const unsigned*)&s_w2lo[r0 + kB];
            alo[m][3] = *(const unsigned*)&s_w2lo[r1 + kB];
        }
        #pragma unroll
        for (int m = 0; m < 4; ++m)
            #pragma unroll
            for (int n = 0; n < 4; ++n)
                mma_bf16(d[m][n], alo[m][0], alo[m][1], alo[m][2], alo[m][3],
                         bhi[n][0], bhi[n][1]);
    }

    // ---- epilogue: max (and min, for s2<0 safety) over points, BN2 ----
    #pragma unroll
    for (int m = 0; m < 4; ++m) {
        float mxA = -FLT_MAX, mnA = FLT_MAX;   // row o = 16m + g
        float mxB = -FLT_MAX, mnB = FLT_MAX;   // row o = 16m + g + 8
        #pragma unroll
        for (int n = 0; n < 4; ++n) {
            mxA = fmaxf(mxA, fmaxf(d[m][n][0], d[m][n][1]));
            mnA = fminf(mnA, fminf(d[m][n][0], d[m][n][1]));
            mxB = fmaxf(mxB, fmaxf(d[m][n][2], d[m][n][3]));
            mnB = fminf(mnB, fminf(d[m][n][2], d[m][n][3]));
        }
        #pragma unroll
        for (int off = 1; off <= 2; off <<= 1) {
            mxA = fmaxf(mxA, __shfl_xor_sync(0xffffffffu, mxA, off));
            mnA = fminf(mnA, __shfl_xor_sync(0xffffffffu, mnA, off));
            mxB = fmaxf(mxB, __shfl_xor_sync(0xffffffffu, mxB, off));
            mnB = fminf(mnB, __shfl_xor_sync(0xffffffffu, mnB, off));
        }
        if (t4 == 0) {
            int oA = 16 * m + g, oB = oA + 8;
            float sA = s_s2[oA], sB = s_s2[oB];
            float vA = (sA >= 0.0f) ? fmaf(sA, mxA, s_t2[oA])
                                    : fmaf(sA, mnA, s_t2[oA]);
            float vB = (sB >= 0.0f) ? fmaf(sB, mxB, s_t2[oB])
                                    : fmaf(sB, mnB, s_t2[oB]);
            g_pooled[pil * 64 + oA] = vA;
            g_pooled[pil * 64 + oB] = vB;
        }
    }
}

// ---------------------------------------------------------------------------
// Kernel 4: emit pseudo-image (B, C, Y, X). grid = (YG, B), 128 threads.
// Thread owns 4 consecutive x. Per c-quad: 4 LDG.128 gathers (L2-resident),
// register transpose, 4 coalesced STG.128.
// ---------------------------------------------------------------------------
__global__ __launch_bounds__(128) void emit_k(float* __restrict__ out) {
    __shared__ int s_wi[XG];
    const int y = blockIdx.x;
    const int b = blockIdx.y;
    for (int x = threadIdx.x; x < XG; x += 128)
        s_wi[x] = g_winner[(b * XG + x) * YG + y];
    __syncthreads();

    const int t = threadIdx.x;
    if (t >= XG / 4) return;   // 108 active threads
    const int x0 = t * 4;

    const float* pp[4];
    bool ok[4];
    #pragma unroll
    for (int i = 0; i < 4; ++i) {
        int wi = s_wi[x0 + i];
        ok[i] = (wi >= 0);
        pp[i] = g_pooled + (ok[i] ? wi : 0) * 64;
    }

    const float4 z4 = make_float4(0.f, 0.f, 0.f, 0.f);
    float* op = out + ((long long)b * CO * YG + y) * XG + x0;
    const long long cstride = (long long)YG * XG;

    #pragma unroll 1
    for (int cq = 0; cq < 16; ++cq) {
        float4 v[4];
        #pragma unroll
        for (int i = 0; i < 4; ++i)
            v[i] = ok[i] ? *(const float4*)(pp[i] + cq * 4) : z4;
        *(float4*)op = make_float4(v[0].x, v[1].x, v[2].x, v[3].x); op += cstride;
        *(float4*)op = make_float4(v[0].y, v[1].y, v[2].y, v[3].y); op += cstride;
        *(float4*)op = make_float4(v[0].z, v[1].z, v[2].z, v[3].z); op += cstride;
        *(float4*)op = make_float4(v[0].w, v[1].w, v[2].w, v[3].w); op += cstride;
    }
}

// ---------------------------------------------------------------------------
// kernel_launch — graph-capturable, allocation-free
// ---------------------------------------------------------------------------
extern "C" void kernel_launch(void* const* d_in, const int* in_sizes, int n_in,
                              void* d_out, int out_size) {
    const float* pillars = (const float*)d_in[0];
    const int*   coors   = (const int*)d_in[1];
    const int*   npts    = (const int*)d_in[2];

    int wbase = (in_sizes[3] == 384) ? 3 : 4;  // skip batch_size slot if present
    const float* W1 = (const float*)d_in[wbase + 0];
    const float* g1 = (const float*)d_in[wbase + 1];
    const float* b1 = (const float*)d_in[wbase + 2];
    const float* m1 = (const float*)d_in[wbase + 3];
    const float* v1 = (const float*)d_in[wbase + 4];
    const float* W2 = (const float*)d_in[wbase + 5];
    const float* g2 = (const float*)d_in[wbase + 6];
    const float* b2 = (const float*)d_in[wbase + 7];
    const float* m2 = (const float*)d_in[wbase + 8];
    const float* v2 = (const float*)d_in[wbase + 9];

    int P = in_sizes[0] / (NPT * 4);
    int B = out_size / (CO * XG * YG);
    if (B > BMAX) B = BMAX;
    if (P > PMAX) P = PMAX;
    int win = B * XG * YG;

    // smem: W2 hi/lo (2*64*HS) + h1 hi/lo (2*8*32*HS) bf16 + s2/t2 floats
    const int smemBytes = (2 * 64 * HS + 2 * 8 * 32 * HS) * 2 + 2 * 64 * 4;
    cudaFuncSetAttribute(mlp_k, cudaFuncAttributeMaxDynamicSharedMemorySize,
                         smemBytes);

    init_winner_k<<<(win + 255) / 256, 256>>>(win);
    winner_k<<<(P + 255) / 256, 256>>>(coors, P, B);
    mlp_k<<<(P + 7) / 8, 256, smemBytes>>>(pillars, coors, npts,
                                           W1, g1, b1, m1, v1,
                                           W2, g2, b2, m2, v2, P);
    emit_k<<<dim3(YG, B), 128>>>((float*)d_out);
}